// round 1
// baseline (speedup 1.0000x reference)
#include <cuda_runtime.h>
#include <cuda_bf16.h>

// Problem constants (fixed by the reference)
#define H 64
#define V 128
#define S 64
#define BATCH 256
#define L 4096

// Scratch (no allocs allowed)
__device__ float d_hn[V * H];      // layernormed hidden per vocab id
__device__ float d_g[V * S];       // gate softmax per vocab id
__device__ int   d_counts[BATCH * V];

// ---------------------------------------------------------------------------
// Kernel 1: per-vocab precompute.  hn[v] = LN(e_v + MLP(e_v)); g[v] = softmax(hn[v]@gate_w+gate_b)
// grid = V blocks, 128 threads
// ---------------------------------------------------------------------------
__global__ void precompute_kernel(const float* __restrict__ embed_w,
                                  const float* __restrict__ w1,
                                  const float* __restrict__ b1,
                                  const float* __restrict__ w2,
                                  const float* __restrict__ b2,
                                  const float* __restrict__ ln_g,
                                  const float* __restrict__ ln_b,
                                  const float* __restrict__ gate_w,
                                  const float* __restrict__ gate_b) {
    int v = blockIdx.x;
    int t = threadIdx.x;  // 0..127
    __shared__ float hs[H];
    __shared__ float us[2 * H];
    __shared__ float xs[H];
    __shared__ float hns[H];
    __shared__ float lg[S];
    __shared__ float red[2];

    if (t < H) hs[t] = embed_w[v * H + t];
    __syncthreads();

    // u = relu(h @ w1 + b1), 128 outputs
    {
        float acc = b1[t];
#pragma unroll
        for (int k = 0; k < H; k++) acc = fmaf(hs[k], w1[k * 128 + t], acc);
        us[t] = fmaxf(acc, 0.0f);
    }
    __syncthreads();

    // ff = u @ w2 + b2; x = h + ff  (64 outputs)
    if (t < H) {
        float acc = b2[t];
#pragma unroll
        for (int k = 0; k < 2 * H; k++) acc = fmaf(us[k], w2[k * H + t], acc);
        xs[t] = hs[t] + acc;
    }
    __syncthreads();

    if (t == 0) {
        float s = 0.0f;
        for (int k = 0; k < H; k++) s += xs[k];
        float mu = s * (1.0f / H);
        float vs = 0.0f;
        for (int k = 0; k < H; k++) { float d = xs[k] - mu; vs += d * d; }
        red[0] = mu;
        red[1] = rsqrtf(vs * (1.0f / H) + 1e-5f);
    }
    __syncthreads();

    if (t < H) {
        float val = (xs[t] - red[0]) * red[1] * ln_g[t] + ln_b[t];
        hns[t] = val;
        d_hn[v * H + t] = val;
    }
    __syncthreads();

    // gate logits + softmax over S=64
    if (t < S) {
        float l = gate_b[t];
#pragma unroll
        for (int k = 0; k < H; k++) l = fmaf(hns[k], gate_w[k * S + t], l);
        lg[t] = l;
    }
    __syncthreads();
    if (t == 0) {
        float m = lg[0];
        for (int k = 1; k < S; k++) m = fmaxf(m, lg[k]);
        float s = 0.0f;
        for (int k = 0; k < S; k++) s += expf(lg[k] - m);
        red[0] = m;
        red[1] = 1.0f / s;
    }
    __syncthreads();
    if (t < S) d_g[v * S + t] = expf(lg[t] - red[0]) * red[1];
}

// ---------------------------------------------------------------------------
// Kernel 2: histogram of seq[b, 0:L-1] over V=128 bins.
// grid = BATCH blocks, 512 threads (16 warps, per-warp sub-histograms)
// ---------------------------------------------------------------------------
__global__ void hist_kernel(const int* __restrict__ seq) {
    int b = blockIdx.x;
    int t = threadIdx.x;
    int w = t >> 5;
    __shared__ int sub[16][V];

    for (int i = t; i < 16 * V; i += 512) ((int*)sub)[i] = 0;
    __syncthreads();

    const int* s = seq + b * L;
    for (int i = t; i < L - 1; i += 512) {
        atomicAdd(&sub[w][s[i]], 1);
    }
    __syncthreads();

    if (t < V) {
        int tot = 0;
#pragma unroll
        for (int k = 0; k < 16; k++) tot += sub[k][t];
        d_counts[b * V + t] = tot;
    }
}

// ---------------------------------------------------------------------------
// Kernel 3: per-batch keys = slot_keys + sum_v c[v] * g[v] x hn[v];
//           cosine attention tail; out = ctx @ out_w + out_b
// grid = BATCH blocks, 64 threads.  Each thread owns a 4(n) x 16(h) tile.
// ---------------------------------------------------------------------------
#define TILE_V 16
__global__ void final_kernel(const int* __restrict__ seq,
                             const float* __restrict__ slot_keys,
                             const float* __restrict__ out_w,
                             const float* __restrict__ out_b,
                             float* __restrict__ out) {
    int b = blockIdx.x;
    int t = threadIdx.x;  // 0..63

    __shared__ float cs[V];
    __shared__ float stage[TILE_V][S];  // g[v][n] * count[v]
    __shared__ float shn[TILE_V][H];
    __shared__ float skeys[S][H + 1];   // pad to avoid bank conflicts
    __shared__ float sq[H];
    __shared__ float ssim[S];
    __shared__ float sattn[S];
    __shared__ float sctx[H];
    __shared__ float red[2];

    // counts -> float
    cs[t]      = (float)d_counts[b * V + t];
    cs[t + 64] = (float)d_counts[b * V + t + 64];
    __syncthreads();

    const int n0 = (t & 15) * 4;
    const int h0 = (t >> 4) * 16;

    float acc[4][16];
#pragma unroll
    for (int j = 0; j < 4; j++)
#pragma unroll
        for (int i = 0; i < 16; i++)
            acc[j][i] = slot_keys[(n0 + j) * H + h0 + i];

    for (int v0 = 0; v0 < V; v0 += TILE_V) {
        // stage TILE_V rows of g (scaled by count) and hn: 2048 floats, float4
        for (int idx = t; idx < TILE_V * S / 4; idx += 64) {
            int vv = idx >> 4;
            int n4 = (idx & 15) * 4;
            float c = cs[v0 + vv];
            float4 gg = *(const float4*)&d_g[(v0 + vv) * S + n4];
            stage[vv][n4 + 0] = gg.x * c;
            stage[vv][n4 + 1] = gg.y * c;
            stage[vv][n4 + 2] = gg.z * c;
            stage[vv][n4 + 3] = gg.w * c;
            *(float4*)&shn[vv][n4] = *(const float4*)&d_hn[(v0 + vv) * H + n4];
        }
        __syncthreads();
#pragma unroll
        for (int vv = 0; vv < TILE_V; vv++) {
            float gn[4];
#pragma unroll
            for (int j = 0; j < 4; j++) gn[j] = stage[vv][n0 + j];
            float hv[16];
#pragma unroll
            for (int i = 0; i < 16; i++) hv[i] = shn[vv][h0 + i];
#pragma unroll
            for (int j = 0; j < 4; j++)
#pragma unroll
                for (int i = 0; i < 16; i++)
                    acc[j][i] = fmaf(gn[j], hv[i], acc[j][i]);
        }
        __syncthreads();
    }

    // keys to shared
#pragma unroll
    for (int j = 0; j < 4; j++)
#pragma unroll
        for (int i = 0; i < 16; i++)
            skeys[n0 + j][h0 + i] = acc[j][i];

    // q = hn[last token]
    {
        int qi = seq[b * L + (L - 1)];
        sq[t] = d_hn[qi * H + t];
    }
    __syncthreads();
    if (t == 0) {
        float s = 0.0f;
        for (int k = 0; k < H; k++) s += sq[k] * sq[k];
        red[0] = 1.0f / fmaxf(sqrtf(s), 1e-12f);
    }
    __syncthreads();
    float qinv = red[0];

    // cosine sim per slot n = t
    {
        float dot = 0.0f, nk = 0.0f;
#pragma unroll
        for (int k = 0; k < H; k++) {
            float kv = skeys[t][k];
            dot = fmaf(kv, sq[k], dot);
            nk = fmaf(kv, kv, nk);
        }
        ssim[t] = dot * qinv / fmaxf(sqrtf(nk), 1e-12f);
    }
    __syncthreads();
    if (t == 0) {
        float m = ssim[0];
        for (int k = 1; k < S; k++) m = fmaxf(m, ssim[k]);
        float s = 0.0f;
        for (int k = 0; k < S; k++) s += expf(ssim[k] - m);
        red[0] = m;
        red[1] = 1.0f / s;
    }
    __syncthreads();
    sattn[t] = expf(ssim[t] - red[0]) * red[1];
    __syncthreads();

    // ctx per h = t (attn-weighted sum of UNNORMALIZED keys: vals = keys)
    {
        float c = 0.0f;
#pragma unroll
        for (int n = 0; n < S; n++) c = fmaf(sattn[n], skeys[n][t], c);
        sctx[t] = c;
    }
    __syncthreads();

    // out[b, j] = ctx @ out_w + out_b, j in [0,128): 2 per thread
#pragma unroll
    for (int jj = 0; jj < 2; jj++) {
        int j = t + jj * 64;
        float o = out_b[j];
#pragma unroll
        for (int k = 0; k < H; k++) o = fmaf(sctx[k], out_w[k * V + j], o);
        out[b * V + j] = o;
    }
}

// ---------------------------------------------------------------------------
extern "C" void kernel_launch(void* const* d_in, const int* in_sizes, int n_in,
                              void* d_out, int out_size) {
    const int*   seq       = (const int*)d_in[0];
    const float* embed_w   = (const float*)d_in[1];
    const float* w1        = (const float*)d_in[2];
    const float* b1        = (const float*)d_in[3];
    const float* w2        = (const float*)d_in[4];
    const float* b2        = (const float*)d_in[5];
    const float* ln_g      = (const float*)d_in[6];
    const float* ln_b      = (const float*)d_in[7];
    const float* slot_keys = (const float*)d_in[8];
    // d_in[9] = slot_vals (unused: reference sets vals = keys)
    const float* gate_w    = (const float*)d_in[10];
    const float* gate_b    = (const float*)d_in[11];
    const float* out_w     = (const float*)d_in[12];
    const float* out_b     = (const float*)d_in[13];
    float* out = (float*)d_out;

    precompute_kernel<<<V, 128>>>(embed_w, w1, b1, w2, b2, ln_g, ln_b, gate_w, gate_b);
    hist_kernel<<<BATCH, 512>>>(seq);
    final_kernel<<<BATCH, 64>>>(seq, slot_keys, out_w, out_b, out);
}

// round 2
// speedup vs baseline: 1.6404x; 1.6404x over previous
#include <cuda_runtime.h>
#include <cuda_bf16.h>

// Problem constants (fixed by the reference)
#define H 64
#define V 128
#define S 64
#define BATCH 256
#define L 4096

// Scratch (no allocs allowed)
__device__ float d_hn[V * H];      // layernormed hidden per vocab id
__device__ float d_g[V * S];       // gate softmax per vocab id
__device__ float d_cnt[BATCH * V]; // histogram (as float)

typedef unsigned long long u64;

__device__ __forceinline__ u64 pack2(float lo, float hi) {
    u64 r;
    asm("mov.b64 %0, {%1, %2};" : "=l"(r) : "f"(lo), "f"(hi));
    return r;
}
__device__ __forceinline__ void fma2(u64& d, u64 a, u64 b) {
    asm("fma.rn.f32x2 %0, %1, %2, %0;" : "+l"(d) : "l"(a), "l"(b));
}
__device__ __forceinline__ void unpack2(float& lo, float& hi, u64 v) {
    asm("mov.b64 {%0, %1}, %2;" : "=f"(lo), "=f"(hi) : "l"(v));
}

// ---------------------------------------------------------------------------
// Kernel 1: blocks [0,128) do per-vocab precompute; blocks [128,384) histogram.
// 256 threads.
// ---------------------------------------------------------------------------
__global__ void prep_hist_kernel(const float* __restrict__ embed_w,
                                 const float* __restrict__ w1,
                                 const float* __restrict__ b1,
                                 const float* __restrict__ w2,
                                 const float* __restrict__ b2,
                                 const float* __restrict__ ln_g,
                                 const float* __restrict__ ln_b,
                                 const float* __restrict__ gate_w,
                                 const float* __restrict__ gate_b,
                                 const int* __restrict__ seq) {
    int t = threadIdx.x;
    int lane = t & 31;
    int warp = t >> 5;

    if (blockIdx.x < V) {
        // ---------------- precompute for vocab v ----------------
        int v = blockIdx.x;
        __shared__ float hs[H];
        __shared__ float us[2 * H];
        __shared__ float hns[H];
        __shared__ float wred[2][2];  // cross-warp reduction scratch

        if (t < H) hs[t] = embed_w[v * H + t];
        __syncthreads();

        // u = relu(h @ w1 + b1): 128 outputs on threads 0..127
        if (t < 2 * H) {
            float acc = b1[t];
#pragma unroll
            for (int k = 0; k < H; k++) acc = fmaf(hs[k], w1[k * (2 * H) + t], acc);
            us[t] = fmaxf(acc, 0.0f);
        }
        __syncthreads();

        float xval = 0.0f;
        if (t < H) {
            float acc = b2[t];
#pragma unroll
            for (int k = 0; k < 2 * H; k++) acc = fmaf(us[k], w2[k * H + t], acc);
            xval = hs[t] + acc;
            // warp-level sum and sumsq (threads 0..63 = warps 0,1)
            float s = xval, sq = xval * xval;
#pragma unroll
            for (int off = 16; off > 0; off >>= 1) {
                s  += __shfl_xor_sync(0xffffffffu, s, off);
                sq += __shfl_xor_sync(0xffffffffu, sq, off);
            }
            if (lane == 0) { wred[warp][0] = s; wred[warp][1] = sq; }
        }
        __syncthreads();

        if (t < H) {
            float s  = wred[0][0] + wred[1][0];
            float sq = wred[0][1] + wred[1][1];
            float mu = s * (1.0f / H);
            float var = sq * (1.0f / H) - mu * mu;
            float rstd = rsqrtf(var + 1e-5f);
            float val = (xval - mu) * rstd * ln_g[t] + ln_b[t];
            hns[t] = val;
            d_hn[v * H + t] = val;
        }
        __syncthreads();

        // gate softmax over S=64 (threads 0..63)
        if (t < S) {
            float l = gate_b[t];
#pragma unroll
            for (int k = 0; k < H; k++) l = fmaf(hns[k], gate_w[k * S + t], l);
            float m = l;
#pragma unroll
            for (int off = 16; off > 0; off >>= 1)
                m = fmaxf(m, __shfl_xor_sync(0xffffffffu, m, off));
            if (lane == 0) wred[warp][0] = m;
            __syncwarp();
            // cross-warp max via shared (both warps must have written)
            __syncthreads();
            m = fmaxf(wred[0][0], wred[1][0]);
            float e = expf(l - m);
            float ssum = e;
#pragma unroll
            for (int off = 16; off > 0; off >>= 1)
                ssum += __shfl_xor_sync(0xffffffffu, ssum, off);
            if (lane == 0) wred[warp][1] = ssum;
            __syncthreads();
            float tot = wred[0][1] + wred[1][1];
            d_g[v * S + t] = e / tot;
        } else {
            __syncthreads();
            __syncthreads();
        }
    } else {
        // ---------------- histogram for batch b ----------------
        int b = blockIdx.x - V;
        __shared__ int sub[8][V];
        for (int i = t; i < 8 * V; i += 256) ((int*)sub)[i] = 0;
        __syncthreads();

        const int4* s4 = (const int4*)(seq + b * L);
        // first L-1 = 4095 tokens: 1023 int4 + 3 scalars
        for (int i = t; i < 1023; i += 256) {
            int4 x = s4[i];
            atomicAdd(&sub[warp][x.x], 1);
            atomicAdd(&sub[warp][x.y], 1);
            atomicAdd(&sub[warp][x.z], 1);
            atomicAdd(&sub[warp][x.w], 1);
        }
        if (t < 3) atomicAdd(&sub[warp][seq[b * L + 4092 + t]], 1);
        __syncthreads();

        if (t < V) {
            int tot = 0;
#pragma unroll
            for (int k = 0; k < 8; k++) tot += sub[k][t];
            d_cnt[b * V + t] = (float)tot;
        }
    }
}

// ---------------------------------------------------------------------------
// Kernel 2: per-batch keys = slot_keys + sum_v c[v] * g[v] x hn[v] (f32x2 FMAs);
//           cosine attention tail; out = ctx @ out_w + out_b.
// grid = BATCH blocks, 64 threads. Each thread owns a 4(n) x 16(h) tile.
// ---------------------------------------------------------------------------
#define TILE_V 16
__global__ void final_kernel(const int* __restrict__ seq,
                             const float* __restrict__ slot_keys,
                             const float* __restrict__ out_w,
                             const float* __restrict__ out_b,
                             float* __restrict__ out) {
    int b = blockIdx.x;
    int t = threadIdx.x;  // 0..63
    int lane = t & 31;
    int warp = t >> 5;

    __shared__ float cs[V];
    __shared__ float stage[TILE_V][S];   // g[v][n] * count[v]
    __shared__ float shn[TILE_V][H];
    __shared__ float skeys[S][H + 1];    // pad to avoid bank conflicts
    __shared__ float sq[H];
    __shared__ float ssim[S];
    __shared__ float sattn[S];
    __shared__ float sctx[H];
    __shared__ float wred[2][2];

    cs[t]      = d_cnt[b * V + t];
    cs[t + 64] = d_cnt[b * V + t + 64];

    const int n0 = (t & 15) * 4;
    const int h0 = (t >> 4) * 16;

    // acc as 4n x 8 f32x2 pairs, init from slot_keys
    u64 acc2[4][8];
#pragma unroll
    for (int j = 0; j < 4; j++) {
        const float2* sk = (const float2*)&slot_keys[(n0 + j) * H + h0];
#pragma unroll
        for (int i = 0; i < 8; i++) {
            float2 kk = sk[i];
            acc2[j][i] = pack2(kk.x, kk.y);
        }
    }
    __syncthreads();

    for (int v0 = 0; v0 < V; v0 += TILE_V) {
        // stage TILE_V rows of g (scaled by count) and hn: float4 loads
        for (int idx = t; idx < TILE_V * S / 4; idx += 64) {
            int vv = idx >> 4;
            int n4 = (idx & 15) * 4;
            float c = cs[v0 + vv];
            float4 gg = *(const float4*)&d_g[(v0 + vv) * S + n4];
            stage[vv][n4 + 0] = gg.x * c;
            stage[vv][n4 + 1] = gg.y * c;
            stage[vv][n4 + 2] = gg.z * c;
            stage[vv][n4 + 3] = gg.w * c;
            *(float4*)&shn[vv][n4] = *(const float4*)&d_hn[(v0 + vv) * H + n4];
        }
        __syncthreads();
#pragma unroll
        for (int vv = 0; vv < TILE_V; vv++) {
            const u64* hp = (const u64*)&shn[vv][h0];
            u64 hv[8];
#pragma unroll
            for (int i = 0; i < 8; i++) hv[i] = hp[i];
#pragma unroll
            for (int j = 0; j < 4; j++) {
                float gf = stage[vv][n0 + j];
                u64 g2 = pack2(gf, gf);
#pragma unroll
                for (int i = 0; i < 8; i++) fma2(acc2[j][i], g2, hv[i]);
            }
        }
        __syncthreads();
    }

    // keys -> shared
#pragma unroll
    for (int j = 0; j < 4; j++)
#pragma unroll
        for (int i = 0; i < 8; i++) {
            float lo, hi;
            unpack2(lo, hi, acc2[j][i]);
            skeys[n0 + j][h0 + 2 * i]     = lo;
            skeys[n0 + j][h0 + 2 * i + 1] = hi;
        }

    // q = hn[last token]
    {
        int qi = seq[b * L + (L - 1)];
        float qv = d_hn[qi * H + t];
        sq[t] = qv;
        float s = qv * qv;
#pragma unroll
        for (int off = 16; off > 0; off >>= 1)
            s += __shfl_xor_sync(0xffffffffu, s, off);
        if (lane == 0) wred[warp][0] = s;
    }
    __syncthreads();
    float qinv = rsqrtf(fmaxf(wred[0][0] + wred[1][0], 1e-24f));

    // cosine sim per slot n = t
    float simv;
    {
        float dot = 0.0f, nk = 0.0f;
#pragma unroll
        for (int k = 0; k < H; k++) {
            float kv = skeys[t][k];
            dot = fmaf(kv, sq[k], dot);
            nk = fmaf(kv, kv, nk);
        }
        simv = dot * qinv / fmaxf(sqrtf(nk), 1e-12f);
        ssim[t] = simv;
        // softmax over 64 via butterfly + cross-warp
        float m = simv;
#pragma unroll
        for (int off = 16; off > 0; off >>= 1)
            m = fmaxf(m, __shfl_xor_sync(0xffffffffu, m, off));
        if (lane == 0) wred[warp][0] = m;
    }
    __syncthreads();
    {
        float m = fmaxf(wred[0][0], wred[1][0]);
        float e = expf(simv - m);
        float s = e;
#pragma unroll
        for (int off = 16; off > 0; off >>= 1)
            s += __shfl_xor_sync(0xffffffffu, s, off);
        if (lane == 0) wred[warp][1] = s;
        __syncthreads();
        float tot = wred[0][1] + wred[1][1];
        sattn[t] = e / tot;
    }
    __syncthreads();

    // ctx per h = t (vals = keys)
    {
        float c = 0.0f;
#pragma unroll
        for (int n = 0; n < S; n++) c = fmaf(sattn[n], skeys[n][t], c);
        sctx[t] = c;
    }
    __syncthreads();

    // out[b, j] = ctx @ out_w + out_b, j in [0,128): 2 per thread
#pragma unroll
    for (int jj = 0; jj < 2; jj++) {
        int j = t + jj * 64;
        float o = out_b[j];
#pragma unroll
        for (int k = 0; k < H; k++) o = fmaf(sctx[k], out_w[k * V + j], o);
        out[b * V + j] = o;
    }
}

// ---------------------------------------------------------------------------
extern "C" void kernel_launch(void* const* d_in, const int* in_sizes, int n_in,
                              void* d_out, int out_size) {
    const int*   seq       = (const int*)d_in[0];
    const float* embed_w   = (const float*)d_in[1];
    const float* w1        = (const float*)d_in[2];
    const float* b1        = (const float*)d_in[3];
    const float* w2        = (const float*)d_in[4];
    const float* b2        = (const float*)d_in[5];
    const float* ln_g      = (const float*)d_in[6];
    const float* ln_b      = (const float*)d_in[7];
    const float* slot_keys = (const float*)d_in[8];
    // d_in[9] = slot_vals (unused: reference sets vals = keys)
    const float* gate_w    = (const float*)d_in[10];
    const float* gate_b    = (const float*)d_in[11];
    const float* out_w     = (const float*)d_in[12];
    const float* out_b     = (const float*)d_in[13];
    float* out = (float*)d_out;

    prep_hist_kernel<<<V + BATCH, 256>>>(embed_w, w1, b1, w2, b2, ln_g, ln_b,
                                         gate_w, gate_b, seq);
    final_kernel<<<BATCH, 64>>>(seq, slot_keys, out_w, out_b, out);
}

// round 3
// speedup vs baseline: 2.0549x; 1.2527x over previous
#include <cuda_runtime.h>
#include <cuda_bf16.h>

// Problem constants (fixed by the reference)
#define H 64
#define V 128
#define S 64
#define BATCH 256
#define L 4096

// Scratch (no allocs allowed)
__device__ float d_hn[V * H];      // layernormed hidden per vocab id
__device__ float d_g[V * S];       // gate softmax per vocab id
__device__ float d_cnt[BATCH * V]; // histogram (as float)

typedef unsigned long long u64;

__device__ __forceinline__ u64 pack2(float lo, float hi) {
    u64 r;
    asm("mov.b64 %0, {%1, %2};" : "=l"(r) : "f"(lo), "f"(hi));
    return r;
}
__device__ __forceinline__ void fma2(u64& d, u64 a, u64 b) {
    asm("fma.rn.f32x2 %0, %1, %2, %0;" : "+l"(d) : "l"(a), "l"(b));
}
__device__ __forceinline__ void unpack2(float& lo, float& hi, u64 v) {
    asm("mov.b64 {%0, %1}, %2;" : "=f"(lo), "=f"(hi) : "l"(v));
}

// ---------------------------------------------------------------------------
// Kernel 1: blocks [0,128) do per-vocab precompute; blocks [128,384) histogram.
// 256 threads.
// ---------------------------------------------------------------------------
__global__ void prep_hist_kernel(const float* __restrict__ embed_w,
                                 const float* __restrict__ w1,
                                 const float* __restrict__ b1,
                                 const float* __restrict__ w2,
                                 const float* __restrict__ b2,
                                 const float* __restrict__ ln_g,
                                 const float* __restrict__ ln_b,
                                 const float* __restrict__ gate_w,
                                 const float* __restrict__ gate_b,
                                 const int* __restrict__ seq) {
    int t = threadIdx.x;
    int lane = t & 31;
    int warp = t >> 5;

    if (blockIdx.x < V) {
        // ---------------- precompute for vocab v ----------------
        int v = blockIdx.x;
        __shared__ float hs[H];
        __shared__ float us[2 * H];
        __shared__ float hns[H];
        __shared__ float wred[2][2];

        if (t < H) hs[t] = embed_w[v * H + t];
        __syncthreads();

        if (t < 2 * H) {
            float acc = b1[t];
#pragma unroll
            for (int k = 0; k < H; k++) acc = fmaf(hs[k], w1[k * (2 * H) + t], acc);
            us[t] = fmaxf(acc, 0.0f);
        }
        __syncthreads();

        float xval = 0.0f;
        if (t < H) {
            float acc = b2[t];
#pragma unroll
            for (int k = 0; k < 2 * H; k++) acc = fmaf(us[k], w2[k * H + t], acc);
            xval = hs[t] + acc;
            float s = xval, sq = xval * xval;
#pragma unroll
            for (int off = 16; off > 0; off >>= 1) {
                s  += __shfl_xor_sync(0xffffffffu, s, off);
                sq += __shfl_xor_sync(0xffffffffu, sq, off);
            }
            if (lane == 0) { wred[warp][0] = s; wred[warp][1] = sq; }
        }
        __syncthreads();

        if (t < H) {
            float s  = wred[0][0] + wred[1][0];
            float sq = wred[0][1] + wred[1][1];
            float mu = s * (1.0f / H);
            float var = sq * (1.0f / H) - mu * mu;
            float rstd = rsqrtf(var + 1e-5f);
            float val = (xval - mu) * rstd * ln_g[t] + ln_b[t];
            hns[t] = val;
            d_hn[v * H + t] = val;
        }
        __syncthreads();

        // gate softmax over S=64 (threads 0..63)
        if (t < S) {
            float l = gate_b[t];
#pragma unroll
            for (int k = 0; k < H; k++) l = fmaf(hns[k], gate_w[k * S + t], l);
            float m = l;
#pragma unroll
            for (int off = 16; off > 0; off >>= 1)
                m = fmaxf(m, __shfl_xor_sync(0xffffffffu, m, off));
            if (lane == 0) wred[warp][0] = m;
            __syncthreads();
            m = fmaxf(wred[0][0], wred[1][0]);
            float e = expf(l - m);
            float ssum = e;
#pragma unroll
            for (int off = 16; off > 0; off >>= 1)
                ssum += __shfl_xor_sync(0xffffffffu, ssum, off);
            if (lane == 0) wred[warp][1] = ssum;
            __syncthreads();
            float tot = wred[0][1] + wred[1][1];
            d_g[v * S + t] = e / tot;
        } else {
            __syncthreads();
            __syncthreads();
        }
    } else {
        // ---------------- histogram for batch b ----------------
        int b = blockIdx.x - V;
        __shared__ int sub[8][V];
        for (int i = t; i < 8 * V; i += 256) ((int*)sub)[i] = 0;
        __syncthreads();

        const int4* s4 = (const int4*)(seq + b * L);
        for (int i = t; i < 1023; i += 256) {
            int4 x = s4[i];
            atomicAdd(&sub[warp][x.x], 1);
            atomicAdd(&sub[warp][x.y], 1);
            atomicAdd(&sub[warp][x.z], 1);
            atomicAdd(&sub[warp][x.w], 1);
        }
        if (t < 3) atomicAdd(&sub[warp][seq[b * L + 4092 + t]], 1);
        __syncthreads();

        if (t < V) {
            int tot = 0;
#pragma unroll
            for (int k = 0; k < 8; k++) tot += sub[k][t];
            d_cnt[b * V + t] = (float)tot;
        }
    }
}

// ---------------------------------------------------------------------------
// Kernel 2: per-batch keys = slot_keys + sum_v c[v]*g[v] x hn[v]  (f32x2 FMAs)
// grid = BATCH blocks, 256 threads. Thread tile: 2(n) x 8(h).
// Ping-pong staging, one barrier per v-tile.
// ---------------------------------------------------------------------------
#define TILE_V 16
#define NTILES (V / TILE_V)
__global__ void __launch_bounds__(256) final_kernel(
        const int* __restrict__ seq,
        const float* __restrict__ slot_keys,
        const float* __restrict__ out_w,
        const float* __restrict__ out_b,
        float* __restrict__ out) {
    int b = blockIdx.x;
    int t = threadIdx.x;  // 0..255
    int lane = t & 31;
    int warp = t >> 5;

    __shared__ float cs[V];
    __shared__ float stage[2][TILE_V][S];   // cg = g[v][n] * count[v], ping-pong
    __shared__ float shn[2][TILE_V][H];
    __shared__ float skeys[S][H + 1];
    __shared__ float sq[H];
    __shared__ float sattn[S];
    __shared__ float sctx[H];
    __shared__ float wredA[2], wredB[2], wredC[2];

    if (t < V) cs[t] = d_cnt[b * V + t];
    __syncthreads();

    const int n0 = (t & 31) * 2;   // 2 slot rows
    const int h0 = (t >> 5) * 8;   // 8 h columns (warp-uniform -> broadcast loads)

    // acc: 2n x 4 u64
    u64 acc2[2][4];
#pragma unroll
    for (int j = 0; j < 2; j++) {
        const float2* sk = (const float2*)&slot_keys[(n0 + j) * H + h0];
#pragma unroll
        for (int i = 0; i < 4; i++) {
            float2 kk = sk[i];
            acc2[j][i] = pack2(kk.x, kk.y);
        }
    }

    // stage tile 0 into buffer 0: each thread handles 1 quad of cg + 1 quad of hn
    {
        int vv = t >> 4;           // 0..15
        int n4 = (t & 15) * 4;
        float c = cs[vv];
        float4 gg = *(const float4*)&d_g[vv * S + n4];
        stage[0][vv][n4 + 0] = gg.x * c;
        stage[0][vv][n4 + 1] = gg.y * c;
        stage[0][vv][n4 + 2] = gg.z * c;
        stage[0][vv][n4 + 3] = gg.w * c;
        *(float4*)&shn[0][vv][n4] = *(const float4*)&d_hn[vv * H + n4];
    }
    __syncthreads();

#pragma unroll
    for (int p = 0; p < NTILES; p++) {
        int cur = p & 1;
        // prefetch next tile into the other buffer
        if (p + 1 < NTILES) {
            int nxt = cur ^ 1;
            int v0 = (p + 1) * TILE_V;
            int vv = t >> 4;
            int n4 = (t & 15) * 4;
            float c = cs[v0 + vv];
            float4 gg = *(const float4*)&d_g[(v0 + vv) * S + n4];
            stage[nxt][vv][n4 + 0] = gg.x * c;
            stage[nxt][vv][n4 + 1] = gg.y * c;
            stage[nxt][vv][n4 + 2] = gg.z * c;
            stage[nxt][vv][n4 + 3] = gg.w * c;
            *(float4*)&shn[nxt][vv][n4] = *(const float4*)&d_hn[(v0 + vv) * H + n4];
        }
#pragma unroll
        for (int vv = 0; vv < TILE_V; vv++) {
            u64 hv[4];
            const u64* hp = (const u64*)&shn[cur][vv][h0];
#pragma unroll
            for (int i = 0; i < 4; i++) hv[i] = hp[i];
            u64 g2 = *(const u64*)&stage[cur][vv][n0];  // [gn0, gn1]
            float g0, g1;
            unpack2(g0, g1, g2);
            u64 ga = pack2(g0, g0), gb = pack2(g1, g1);
#pragma unroll
            for (int i = 0; i < 4; i++) fma2(acc2[0][i], ga, hv[i]);
#pragma unroll
            for (int i = 0; i < 4; i++) fma2(acc2[1][i], gb, hv[i]);
        }
        __syncthreads();
    }

    // keys -> shared
#pragma unroll
    for (int j = 0; j < 2; j++)
#pragma unroll
        for (int i = 0; i < 4; i++) {
            float lo, hi;
            unpack2(lo, hi, acc2[j][i]);
            skeys[n0 + j][h0 + 2 * i]     = lo;
            skeys[n0 + j][h0 + 2 * i + 1] = hi;
        }

    // q = hn[last token]; q norm (warps 0,1)
    int qi = seq[b * L + (L - 1)];
    if (t < H) {
        float qv = d_hn[qi * H + t];
        sq[t] = qv;
        float s = qv * qv;
#pragma unroll
        for (int off = 16; off > 0; off >>= 1)
            s += __shfl_xor_sync(0xffffffffu, s, off);
        if (lane == 0) wredA[warp] = s;
    }
    __syncthreads();

    float simv = 0.0f;
    if (t < S) {
        float qinv = rsqrtf(fmaxf(wredA[0] + wredA[1], 1e-24f));
        float dot = 0.0f, nk = 0.0f;
#pragma unroll
        for (int k = 0; k < H; k++) {
            float kv = skeys[t][k];
            dot = fmaf(kv, sq[k], dot);
            nk = fmaf(kv, kv, nk);
        }
        simv = dot * qinv / fmaxf(sqrtf(nk), 1e-12f);
        float m = simv;
#pragma unroll
        for (int off = 16; off > 0; off >>= 1)
            m = fmaxf(m, __shfl_xor_sync(0xffffffffu, m, off));
        if (lane == 0) wredB[warp] = m;
    }
    __syncthreads();

    float ev = 0.0f;
    if (t < S) {
        float m = fmaxf(wredB[0], wredB[1]);
        ev = expf(simv - m);
        float s = ev;
#pragma unroll
        for (int off = 16; off > 0; off >>= 1)
            s += __shfl_xor_sync(0xffffffffu, s, off);
        if (lane == 0) wredC[warp] = s;
    }
    __syncthreads();

    if (t < S) sattn[t] = ev / (wredC[0] + wredC[1]);
    __syncthreads();

    if (t < H) {
        float c = 0.0f;
#pragma unroll
        for (int n = 0; n < S; n++) c = fmaf(sattn[n], skeys[n][t], c);
        sctx[t] = c;
    }
    __syncthreads();

    // out[b, j] = ctx @ out_w + out_b (threads 0..127)
    if (t < V) {
        float o = out_b[t];
#pragma unroll
        for (int k = 0; k < H; k++) o = fmaf(sctx[k], out_w[k * V + t], o);
        out[b * V + t] = o;
    }
}

// ---------------------------------------------------------------------------
extern "C" void kernel_launch(void* const* d_in, const int* in_sizes, int n_in,
                              void* d_out, int out_size) {
    const int*   seq       = (const int*)d_in[0];
    const float* embed_w   = (const float*)d_in[1];
    const float* w1        = (const float*)d_in[2];
    const float* b1        = (const float*)d_in[3];
    const float* w2        = (const float*)d_in[4];
    const float* b2        = (const float*)d_in[5];
    const float* ln_g      = (const float*)d_in[6];
    const float* ln_b      = (const float*)d_in[7];
    const float* slot_keys = (const float*)d_in[8];
    // d_in[9] = slot_vals (unused: reference sets vals = keys)
    const float* gate_w    = (const float*)d_in[10];
    const float* gate_b    = (const float*)d_in[11];
    const float* out_w     = (const float*)d_in[12];
    const float* out_b     = (const float*)d_in[13];
    float* out = (float*)d_out;

    prep_hist_kernel<<<V + BATCH, 256>>>(embed_w, w1, b1, w2, b2, ln_g, ln_b,
                                         gate_w, gate_b, seq);
    final_kernel<<<BATCH, 256>>>(seq, slot_keys, out_w, out_b, out);
}

// round 4
// speedup vs baseline: 2.0606x; 1.0028x over previous
#include <cuda_runtime.h>
#include <cuda_bf16.h>

// Problem constants (fixed by the reference)
#define H 64
#define V 128
#define S 64
#define BATCH 256
#define L 4096

// Scratch (no allocs allowed)
__device__ float d_hn[V * H];      // layernormed hidden per vocab id
__device__ float d_g[V * S];       // gate softmax per vocab id
__device__ float d_cnt[BATCH * V]; // histogram (as float)

typedef unsigned long long u64;

__device__ __forceinline__ u64 pack2(float lo, float hi) {
    u64 r;
    asm("mov.b64 %0, {%1, %2};" : "=l"(r) : "f"(lo), "f"(hi));
    return r;
}
__device__ __forceinline__ void fma2(u64& d, u64 a, u64 b) {
    asm("fma.rn.f32x2 %0, %1, %2, %0;" : "+l"(d) : "l"(a), "l"(b));
}
__device__ __forceinline__ void unpack2(float& lo, float& hi, u64 v) {
    asm("mov.b64 {%0, %1}, %2;" : "=f"(lo), "=f"(hi) : "l"(v));
}

// ---------------------------------------------------------------------------
// Kernel 1: blocks [0,128) do per-vocab precompute; blocks [128,384) histogram.
// 256 threads.
// ---------------------------------------------------------------------------
__global__ void prep_hist_kernel(const float* __restrict__ embed_w,
                                 const float* __restrict__ w1,
                                 const float* __restrict__ b1,
                                 const float* __restrict__ w2,
                                 const float* __restrict__ b2,
                                 const float* __restrict__ ln_g,
                                 const float* __restrict__ ln_b,
                                 const float* __restrict__ gate_w,
                                 const float* __restrict__ gate_b,
                                 const int* __restrict__ seq) {
    int t = threadIdx.x;
    int lane = t & 31;
    int warp = t >> 5;

    if (blockIdx.x < V) {
        // ---------------- precompute for vocab v ----------------
        int v = blockIdx.x;
        __shared__ float hs[H];
        __shared__ float us[2 * H];
        __shared__ float hns[H];
        __shared__ float wred[2][2];

        if (t < H) hs[t] = embed_w[v * H + t];
        __syncthreads();

        if (t < 2 * H) {
            float acc = b1[t];
#pragma unroll
            for (int k = 0; k < H; k++) acc = fmaf(hs[k], w1[k * (2 * H) + t], acc);
            us[t] = fmaxf(acc, 0.0f);
        }
        __syncthreads();

        float xval = 0.0f;
        if (t < H) {
            float acc = b2[t];
#pragma unroll
            for (int k = 0; k < 2 * H; k++) acc = fmaf(us[k], w2[k * H + t], acc);
            xval = hs[t] + acc;
            float s = xval, sq = xval * xval;
#pragma unroll
            for (int off = 16; off > 0; off >>= 1) {
                s  += __shfl_xor_sync(0xffffffffu, s, off);
                sq += __shfl_xor_sync(0xffffffffu, sq, off);
            }
            if (lane == 0) { wred[warp][0] = s; wred[warp][1] = sq; }
        }
        __syncthreads();

        if (t < H) {
            float s  = wred[0][0] + wred[1][0];
            float sq = wred[0][1] + wred[1][1];
            float mu = s * (1.0f / H);
            float var = sq * (1.0f / H) - mu * mu;
            float rstd = rsqrtf(var + 1e-5f);
            float val = (xval - mu) * rstd * ln_g[t] + ln_b[t];
            hns[t] = val;
            d_hn[v * H + t] = val;
        }
        __syncthreads();

        // gate softmax over S=64 (threads 0..63)
        if (t < S) {
            float l = gate_b[t];
#pragma unroll
            for (int k = 0; k < H; k++) l = fmaf(hns[k], gate_w[k * S + t], l);
            float m = l;
#pragma unroll
            for (int off = 16; off > 0; off >>= 1)
                m = fmaxf(m, __shfl_xor_sync(0xffffffffu, m, off));
            if (lane == 0) wred[warp][0] = m;
            __syncthreads();
            m = fmaxf(wred[0][0], wred[1][0]);
            float e = expf(l - m);
            float ssum = e;
#pragma unroll
            for (int off = 16; off > 0; off >>= 1)
                ssum += __shfl_xor_sync(0xffffffffu, ssum, off);
            if (lane == 0) wred[warp][1] = ssum;
            __syncthreads();
            float tot = wred[0][1] + wred[1][1];
            d_g[v * S + t] = e / tot;
        } else {
            __syncthreads();
            __syncthreads();
        }
    } else {
        // ---------------- histogram for batch b ----------------
        int b = blockIdx.x - V;
        __shared__ int sub[8][V];
        for (int i = t; i < 8 * V; i += 256) ((int*)sub)[i] = 0;
        __syncthreads();

        const int4* s4 = (const int4*)(seq + b * L);
        for (int i = t; i < 1023; i += 256) {
            int4 x = s4[i];
            atomicAdd(&sub[warp][x.x], 1);
            atomicAdd(&sub[warp][x.y], 1);
            atomicAdd(&sub[warp][x.z], 1);
            atomicAdd(&sub[warp][x.w], 1);
        }
        if (t < 3) atomicAdd(&sub[warp][seq[b * L + 4092 + t]], 1);
        __syncthreads();

        if (t < V) {
            int tot = 0;
#pragma unroll
            for (int k = 0; k < 8; k++) tot += sub[k][t];
            d_cnt[b * V + t] = (float)tot;
        }
    }
}

// ---------------------------------------------------------------------------
// Kernel 2: per-batch keys = slot_keys + sum_v c[v]*g[v] x hn[v]  (f32x2 FMAs)
// grid = BATCH blocks, 128 threads. Thread tile: 4(n) x 16(h).
// Per vv: 1 LDS.128 (gn) + 2 LDS.128 (hv) + 16 FMA2  -> fma-pipe-bound.
// ---------------------------------------------------------------------------
#define TILE_V 16
#define NTILES (V / TILE_V)
__global__ void __launch_bounds__(128) final_kernel(
        const int* __restrict__ seq,
        const float* __restrict__ slot_keys,
        const float* __restrict__ out_w,
        const float* __restrict__ out_b,
        float* __restrict__ out) {
    int b = blockIdx.x;
    int t = threadIdx.x;  // 0..127
    int lane = t & 31;
    int warp = t >> 5;

    __shared__ float cs[V];
    __shared__ float stage[2][TILE_V][S];   // cg = g[v][n] * count[v], ping-pong
    __shared__ float shn[2][TILE_V][H];
    __shared__ float skeys[S][H + 1];
    __shared__ float sq[H];
    __shared__ float sattn[S];
    __shared__ float sctx[H];
    __shared__ float wredA[2], wredB[2], wredC[2];

    cs[t] = d_cnt[b * V + t];
    __syncthreads();

    const int n0 = (t & 15) * 4;   // 4 slot rows (16B aligned in stage)
    const int h0 = (t >> 4) * 8;   // 8 h columns = 8 f32x2 ... (16 floats? no: 8 floats, 4 u64)

    // acc: 4n x 4 u64 (each u64 = 2 h) -> 4n x 8h floats
    u64 acc2[4][4];
#pragma unroll
    for (int j = 0; j < 4; j++) {
        const float2* sk = (const float2*)&slot_keys[(n0 + j) * H + h0];
#pragma unroll
        for (int i = 0; i < 4; i++) {
            float2 kk = sk[i];
            acc2[j][i] = pack2(kk.x, kk.y);
        }
    }

    // stage tile 0 into buffer 0 (cg: 256 quads, hn: 256 quads; 128 threads)
    {
#pragma unroll
        for (int idx = t; idx < TILE_V * S / 4; idx += 128) {
            int vv = idx >> 4;
            int n4 = (idx & 15) * 4;
            float c = cs[vv];
            float4 gg = *(const float4*)&d_g[vv * S + n4];
            stage[0][vv][n4 + 0] = gg.x * c;
            stage[0][vv][n4 + 1] = gg.y * c;
            stage[0][vv][n4 + 2] = gg.z * c;
            stage[0][vv][n4 + 3] = gg.w * c;
            *(float4*)&shn[0][vv][n4] = *(const float4*)&d_hn[vv * H + n4];
        }
    }
    __syncthreads();

#pragma unroll
    for (int p = 0; p < NTILES; p++) {
        int cur = p & 1;
        if (p + 1 < NTILES) {
            int nxt = cur ^ 1;
            int v0 = (p + 1) * TILE_V;
#pragma unroll
            for (int idx = t; idx < TILE_V * S / 4; idx += 128) {
                int vv = idx >> 4;
                int n4 = (idx & 15) * 4;
                float c = cs[v0 + vv];
                float4 gg = *(const float4*)&d_g[(v0 + vv) * S + n4];
                stage[nxt][vv][n4 + 0] = gg.x * c;
                stage[nxt][vv][n4 + 1] = gg.y * c;
                stage[nxt][vv][n4 + 2] = gg.z * c;
                stage[nxt][vv][n4 + 3] = gg.w * c;
                *(float4*)&shn[nxt][vv][n4] = *(const float4*)&d_hn[(v0 + vv) * H + n4];
            }
        }
#pragma unroll
        for (int vv = 0; vv < TILE_V; vv++) {
            // 8 h floats = 4 u64
            u64 hv[4];
            const u64* hp = (const u64*)&shn[cur][vv][h0];
#pragma unroll
            for (int i = 0; i < 4; i++) hv[i] = hp[i];
            // 4 gate values (one LDS.128)
            float4 gq = *(const float4*)&stage[cur][vv][n0];
            u64 g2[4];
            g2[0] = pack2(gq.x, gq.x);
            g2[1] = pack2(gq.y, gq.y);
            g2[2] = pack2(gq.z, gq.z);
            g2[3] = pack2(gq.w, gq.w);
#pragma unroll
            for (int j = 0; j < 4; j++)
#pragma unroll
                for (int i = 0; i < 4; i++)
                    fma2(acc2[j][i], g2[j], hv[i]);
        }
        __syncthreads();
    }

    // keys -> shared
#pragma unroll
    for (int j = 0; j < 4; j++)
#pragma unroll
        for (int i = 0; i < 4; i++) {
            float lo, hi;
            unpack2(lo, hi, acc2[j][i]);
            skeys[n0 + j][h0 + 2 * i]     = lo;
            skeys[n0 + j][h0 + 2 * i + 1] = hi;
        }

    // q = hn[last token]; q norm (warps 0,1)
    int qi = seq[b * L + (L - 1)];
    if (t < H) {
        float qv = d_hn[qi * H + t];
        sq[t] = qv;
        float s = qv * qv;
#pragma unroll
        for (int off = 16; off > 0; off >>= 1)
            s += __shfl_xor_sync(0xffffffffu, s, off);
        if (lane == 0) wredA[warp] = s;
    }
    __syncthreads();

    float simv = 0.0f;
    if (t < S) {
        float qinv = rsqrtf(fmaxf(wredA[0] + wredA[1], 1e-24f));
        float dot = 0.0f, nk = 0.0f;
#pragma unroll
        for (int k = 0; k < H; k++) {
            float kv = skeys[t][k];
            dot = fmaf(kv, sq[k], dot);
            nk = fmaf(kv, kv, nk);
        }
        simv = dot * qinv / fmaxf(sqrtf(nk), 1e-12f);
        float m = simv;
#pragma unroll
        for (int off = 16; off > 0; off >>= 1)
            m = fmaxf(m, __shfl_xor_sync(0xffffffffu, m, off));
        if (lane == 0) wredB[warp] = m;
    }
    __syncthreads();

    float ev = 0.0f;
    if (t < S) {
        float m = fmaxf(wredB[0], wredB[1]);
        ev = expf(simv - m);
        float s = ev;
#pragma unroll
        for (int off = 16; off > 0; off >>= 1)
            s += __shfl_xor_sync(0xffffffffu, s, off);
        if (lane == 0) wredC[warp] = s;
    }
    __syncthreads();

    if (t < S) sattn[t] = ev / (wredC[0] + wredC[1]);
    __syncthreads();

    if (t < H) {
        float c = 0.0f;
#pragma unroll
        for (int n = 0; n < S; n++) c = fmaf(sattn[n], skeys[n][t], c);
        sctx[t] = c;
    }
    __syncthreads();

    // out[b, j] = ctx @ out_w + out_b (all 128 threads, 1 column each)
    {
        float o = out_b[t];
#pragma unroll
        for (int k = 0; k < H; k++) o = fmaf(sctx[k], out_w[k * V + t], o);
        out[b * V + t] = o;
    }
}

// ---------------------------------------------------------------------------
extern "C" void kernel_launch(void* const* d_in, const int* in_sizes, int n_in,
                              void* d_out, int out_size) {
    const int*   seq       = (const int*)d_in[0];
    const float* embed_w   = (const float*)d_in[1];
    const float* w1        = (const float*)d_in[2];
    const float* b1        = (const float*)d_in[3];
    const float* w2        = (const float*)d_in[4];
    const float* b2        = (const float*)d_in[5];
    const float* ln_g      = (const float*)d_in[6];
    const float* ln_b      = (const float*)d_in[7];
    const float* slot_keys = (const float*)d_in[8];
    // d_in[9] = slot_vals (unused: reference sets vals = keys)
    const float* gate_w    = (const float*)d_in[10];
    const float* gate_b    = (const float*)d_in[11];
    const float* out_w     = (const float*)d_in[12];
    const float* out_b     = (const float*)d_in[13];
    float* out = (float*)d_out;

    prep_hist_kernel<<<V + BATCH, 256>>>(embed_w, w1, b1, w2, b2, ln_g, ln_b,
                                         gate_w, gate_b, seq);
    final_kernel<<<BATCH, 128>>>(seq, slot_keys, out_w, out_b, out);
}